// round 1
// baseline (speedup 1.0000x reference)
#include <cuda_runtime.h>
#include <math.h>

// ---------------- problem constants ----------------
#define BB 4
#define LL 2048
#define DD 192
#define DI 384
#define DS 64
#define DR 12
#define NXDB (DR + DS)      // 76
#define BL (BB * LL)        // 8192

// ---------------- scratch (static device globals; no allocation) ----------------
__device__ float  g_h[(size_t)BL * DD];            // LN output
__device__ float  g_xz[(size_t)BL * 2 * DI];       // x | z
__device__ float  g_xconv[(size_t)BL * DI];        // conv+silu output (u)
__device__ float  g_xdb[(size_t)BL * NXDB];        // [dt_rank | B-matrix]
__device__ float  g_G[(size_t)BL * DS];            // C_n * B[b,t,n]
__device__ float4 g_P[(size_t)BB * DI * LL];       // packed (dt, dt*u, u*D, silu(z)) transposed (b,d,t)
__device__ float  g_y[(size_t)BL * DI];            // scan output (pre W_out)
__device__ float  g_A[DI * DS];                    // A = -exp(A_log)

// ---------------- kernel 0: A = -exp(A_log) ----------------
__global__ void prep_A_kernel(const float* __restrict__ A_log) {
    int i = blockIdx.x * blockDim.x + threadIdx.x;
    if (i < DI * DS) g_A[i] = -expf(A_log[i]);
}

// ---------------- kernel 1: residual += hidden; LayerNorm -> h ----------------
__global__ void ln_kernel(const float* __restrict__ hid, const float* __restrict__ res,
                          const float* __restrict__ lw, const float* __restrict__ lb,
                          float* __restrict__ res_out) {
    int row  = blockIdx.x * (blockDim.x >> 5) + (threadIdx.x >> 5);
    int lane = threadIdx.x & 31;
    if (row >= BL) return;
    const float* hr = hid + (size_t)row * DD;
    const float* rr = res + (size_t)row * DD;
    float v[6];
    float sum = 0.f, sq = 0.f;
#pragma unroll
    for (int i = 0; i < 6; i++) {
        v[i] = hr[lane + 32 * i] + rr[lane + 32 * i];
        sum += v[i];
        sq  = fmaf(v[i], v[i], sq);
    }
#pragma unroll
    for (int m = 16; m >= 1; m >>= 1) {
        sum += __shfl_xor_sync(0xffffffffu, sum, m);
        sq  += __shfl_xor_sync(0xffffffffu, sq,  m);
    }
    float mu  = sum * (1.f / DD);
    float var = sq * (1.f / DD) - mu * mu;
    float inv = rsqrtf(var + 1e-5f);
#pragma unroll
    for (int i = 0; i < 6; i++) {
        int c = lane + 32 * i;
        res_out[(size_t)row * DD + c] = v[i];
        g_h[(size_t)row * DD + c] = (v[i] - mu) * inv * lw[c] + lb[c];
    }
}

// ---------------- generic fp32 GEMM: C[M,N] = A[M,K] * W[N,K]^T ----------------
template <int BM, int BN, int BK, int TM, int TN>
__global__ void gemm_nt(const float* __restrict__ A, const float* __restrict__ W,
                        float* __restrict__ C, int M, int N, int K) {
    __shared__ float As[BK][BM + 1];
    __shared__ float Ws[BK][BN + 1];
    const int bm = blockIdx.y * BM;
    const int bn = blockIdx.x * BN;
    const int tid = threadIdx.x;              // 256 threads
    const int tx = tid % (BN / TN);           // N dir
    const int ty = tid / (BN / TN);           // M dir
    float acc[TM][TN];
#pragma unroll
    for (int i = 0; i < TM; i++)
#pragma unroll
        for (int j = 0; j < TN; j++) acc[i][j] = 0.f;

    for (int k0 = 0; k0 < K; k0 += BK) {
#pragma unroll
        for (int i = tid; i < BM * BK; i += 256) {
            int m = i / BK, k = i % BK;
            As[k][m] = A[(size_t)(bm + m) * K + k0 + k];
        }
#pragma unroll
        for (int i = tid; i < BN * BK; i += 256) {
            int n = i / BK, k = i % BK;
            float v = 0.f;
            if (bn + n < N) v = W[(size_t)(bn + n) * K + k0 + k];
            Ws[k][n] = v;
        }
        __syncthreads();
#pragma unroll
        for (int k = 0; k < BK; ++k) {
            float a[TM], w[TN];
#pragma unroll
            for (int i = 0; i < TM; i++) a[i] = As[k][ty * TM + i];
#pragma unroll
            for (int j = 0; j < TN; j++) w[j] = Ws[k][tx * TN + j];
#pragma unroll
            for (int i = 0; i < TM; i++)
#pragma unroll
                for (int j = 0; j < TN; j++) acc[i][j] = fmaf(a[i], w[j], acc[i][j]);
        }
        __syncthreads();
    }
#pragma unroll
    for (int i = 0; i < TM; i++) {
        int m = bm + ty * TM + i;
#pragma unroll
        for (int j = 0; j < TN; j++) {
            int n = bn + tx * TN + j;
            if (n < N) C[(size_t)m * N + n] = acc[i][j];
        }
    }
}

// ---------------- kernel 3: depthwise causal conv (k=4) + SiLU ----------------
__global__ void conv_kernel(const float* __restrict__ conv_w, const float* __restrict__ conv_b) {
    size_t idx = (size_t)blockIdx.x * blockDim.x + threadIdx.x;
    if (idx >= (size_t)BL * DI) return;
    int d = (int)(idx % DI);
    size_t bl = idx / DI;
    int l = (int)(bl % LL);
    float w0 = conv_w[d * 4 + 0], w1 = conv_w[d * 4 + 1];
    float w2 = conv_w[d * 4 + 2], w3 = conv_w[d * 4 + 3];
    const float* base = g_xz + bl * (2 * DI) + d;   // x column at (b,l)
    float acc = conv_b[d];
    acc = fmaf(w3, base[0], acc);
    if (l >= 1) acc = fmaf(w2, base[-(2 * DI)], acc);
    if (l >= 2) acc = fmaf(w1, base[-(4 * DI)], acc);
    if (l >= 3) acc = fmaf(w0, base[-(6 * DI)], acc);
    // silu
    float s = acc / (1.f + expf(-acc));
    g_xconv[idx] = s;
}

// ---------------- kernel 5: fold C into B-matrix: G = C_n * xdb[..., 12+n] ----------------
__global__ void scaleG_kernel(const float* __restrict__ Cf) {
    size_t i = (size_t)blockIdx.x * blockDim.x + threadIdx.x;
    if (i >= (size_t)BL * DS) return;
    int n = (int)(i % DS);
    size_t bl = i / DS;
    g_G[i] = g_xdb[bl * NXDB + DR + n] * Cf[n];
}

// ---------------- kernel 6: dt projection + softplus + pack transposed float4 ----------------
__global__ void dtpack_kernel(const float* __restrict__ W_dt, const float* __restrict__ b_dt,
                              const float* __restrict__ D_skip) {
    int bl = blockIdx.x;          // 0..BL-1
    int d  = threadIdx.x;         // 0..383
    __shared__ float sx[DR];
    if (d < DR) sx[d] = g_xdb[(size_t)bl * NXDB + d];
    __syncthreads();
    float acc = b_dt[d];
#pragma unroll
    for (int r = 0; r < DR; r++) acc = fmaf(sx[r], W_dt[d * DR + r], acc);
    // softplus (stable)
    float dt = fmaxf(acc, 0.f) + log1pf(expf(-fabsf(acc)));
    float xc = g_xconv[(size_t)bl * DI + d];
    float z  = g_xz[(size_t)bl * (2 * DI) + DI + d];
    float sz = z / (1.f + expf(-z));
    int b = bl / LL, l = bl % LL;
    g_P[((size_t)(b * DI + d)) * LL + l] = make_float4(dt, dt * xc, xc * D_skip[d], sz);
}

// ---------------- kernel 7: selective scan (one warp per (b,d)) ----------------
__global__ void __launch_bounds__(128) scan_kernel() {
    int warp = (blockIdx.x * blockDim.x + threadIdx.x) >> 5;
    int lane = threadIdx.x & 31;
    if (warp >= BB * DI) return;
    int b = warp / DI;
    int d = warp % DI;

    const float4* __restrict__ p  = g_P + (size_t)warp * LL;
    const float2* __restrict__ Gp = reinterpret_cast<const float2*>(g_G + (size_t)b * LL * DS);
    float* __restrict__ yp = g_y + (size_t)b * LL * DI + d;

    const float A1 = g_A[d * DS + 2 * lane];
    const float A2 = g_A[d * DS + 2 * lane + 1];

    float h1 = 0.f, h2 = 0.f;
    float4 pk = p[0];
    float2 gv = Gp[lane];

#pragma unroll 4
    for (int t = 0; t < LL; ++t) {
        float4 pk_n;
        float2 gv_n;
        if (t + 1 < LL) {
            pk_n = p[t + 1];
            gv_n = Gp[(t + 1) * (DS / 2) + lane];
        }
        float e1 = __expf(A1 * pk.x);
        float e2 = __expf(A2 * pk.x);
        h1 = fmaf(e1, h1, pk.y * gv.x);
        h2 = fmaf(e2, h2, pk.y * gv.y);
        float s = h1 + h2;
        s += __shfl_xor_sync(0xffffffffu, s, 16);
        s += __shfl_xor_sync(0xffffffffu, s, 8);
        s += __shfl_xor_sync(0xffffffffu, s, 4);
        s += __shfl_xor_sync(0xffffffffu, s, 2);
        s += __shfl_xor_sync(0xffffffffu, s, 1);
        if (lane == 0) yp[(size_t)t * DI] = (s + pk.z) * pk.w;
        pk = pk_n;
        gv = gv_n;
    }
}

// ---------------- launch ----------------
extern "C" void kernel_launch(void* const* d_in, const int* in_sizes, int n_in,
                              void* d_out, int out_size) {
    const float* hidden  = (const float*)d_in[0];
    const float* resid   = (const float*)d_in[1];
    const float* ln_w    = (const float*)d_in[2];
    const float* ln_b    = (const float*)d_in[3];
    const float* W_in    = (const float*)d_in[4];
    const float* conv_w  = (const float*)d_in[5];
    const float* conv_b  = (const float*)d_in[6];
    const float* W_xproj = (const float*)d_in[7];
    const float* W_dt    = (const float*)d_in[8];
    const float* b_dt    = (const float*)d_in[9];
    const float* A_log   = (const float*)d_in[10];
    const float* D_skip  = (const float*)d_in[11];
    const float* C_fixed = (const float*)d_in[12];
    const float* W_out   = (const float*)d_in[13];

    float* out      = (float*)d_out;                 // (B,L,D)
    float* res_out  = (float*)d_out + (size_t)BL * DD; // (B,L,D)

    // device pointers to scratch symbols (kernels use globals directly)
    float* d_h;     cudaGetSymbolAddress((void**)&d_h, g_h);
    float* d_xz;    cudaGetSymbolAddress((void**)&d_xz, g_xz);
    float* d_xc;    cudaGetSymbolAddress((void**)&d_xc, g_xconv);
    float* d_xdb;   cudaGetSymbolAddress((void**)&d_xdb, g_xdb);
    float* d_y;     cudaGetSymbolAddress((void**)&d_y, g_y);

    // 0) A = -exp(A_log)
    prep_A_kernel<<<(DI * DS + 255) / 256, 256>>>(A_log);

    // 1) residual add + LN
    ln_kernel<<<BL / 8, 256>>>(hidden, resid, ln_w, ln_b, res_out);

    // 2) xz = h @ W_in^T   (M=8192, N=768, K=192)
    {
        dim3 grid(768 / 64, BL / 128);
        gemm_nt<128, 64, 16, 8, 4><<<grid, 256>>>(d_h, W_in, d_xz, BL, 2 * DI, DD);
    }

    // 3) depthwise causal conv + silu
    conv_kernel<<<((size_t)BL * DI + 255) / 256, 256>>>(conv_w, conv_b);

    // 4) xdb = xconv @ W_xproj^T  (M=8192, N=76, K=384)
    {
        dim3 grid((NXDB + 63) / 64, BL / 128);
        gemm_nt<128, 64, 16, 8, 4><<<grid, 256>>>(d_xc, W_xproj, d_xdb, BL, NXDB, DI);
    }

    // 5) G = C * B
    scaleG_kernel<<<((size_t)BL * DS + 255) / 256, 256>>>(C_fixed);

    // 6) dt / pack
    dtpack_kernel<<<BL, DI>>>(W_dt, b_dt, D_skip);

    // 7) scan
    scan_kernel<<<(BB * DI) / 4, 128>>>();

    // 8) out = y @ W_out^T  (M=8192, N=192, K=384)
    {
        dim3 grid(DD / 64, BL / 128);
        gemm_nt<128, 64, 16, 8, 4><<<grid, 256>>>(d_y, W_out, out, BL, DD, DI);
    }
}

// round 10
// speedup vs baseline: 1.4962x; 1.4962x over previous
#include <cuda_runtime.h>
#include <math.h>
#include <stdint.h>

// ---------------- problem constants ----------------
#define BB 4
#define LL 2048
#define DD 192
#define DI 384
#define DS 64
#define DR 12
#define NXDB (DR + DS)      // 76
#define BL (BB * LL)        // 8192

// ---------------- scratch (static device globals; no allocation) ----------------
__device__ float  g_h[(size_t)BL * DD];            // LN output
__device__ float  g_xz[(size_t)BL * 2 * DI];       // x | z
__device__ float  g_xconv[(size_t)BL * DI];        // conv+silu output (u)
__device__ float  g_xdb[(size_t)BL * NXDB];        // [dt_rank | B-matrix]
__device__ float  g_G[(size_t)BL * DS];            // C_n * B[b,t,n]
__device__ float4 g_P[(size_t)BB * DI * LL];       // packed (dt, dt*u, u*D, silu(z)), (b,d,t)
__device__ float  g_y[(size_t)BB * DI * LL];       // scan output, TRANSPOSED [b][d][t]
__device__ float  g_A[DI * DS];                    // A = -exp(A_log)

// ---------------- kernel 0: A = -exp(A_log) ----------------
__global__ void prep_A_kernel(const float* __restrict__ A_log) {
    int i = blockIdx.x * blockDim.x + threadIdx.x;
    if (i < DI * DS) g_A[i] = -expf(A_log[i]);
}

// ---------------- kernel 1: residual += hidden; LayerNorm -> h ----------------
__global__ void ln_kernel(const float* __restrict__ hid, const float* __restrict__ res,
                          const float* __restrict__ lw, const float* __restrict__ lb,
                          float* __restrict__ res_out) {
    int row  = blockIdx.x * (blockDim.x >> 5) + (threadIdx.x >> 5);
    int lane = threadIdx.x & 31;
    if (row >= BL) return;
    const float* hr = hid + (size_t)row * DD;
    const float* rr = res + (size_t)row * DD;
    float v[6];
    float sum = 0.f, sq = 0.f;
#pragma unroll
    for (int i = 0; i < 6; i++) {
        v[i] = hr[lane + 32 * i] + rr[lane + 32 * i];
        sum += v[i];
        sq  = fmaf(v[i], v[i], sq);
    }
#pragma unroll
    for (int m = 16; m >= 1; m >>= 1) {
        sum += __shfl_xor_sync(0xffffffffu, sum, m);
        sq  += __shfl_xor_sync(0xffffffffu, sq,  m);
    }
    float mu  = sum * (1.f / DD);
    float var = sq * (1.f / DD) - mu * mu;
    float inv = rsqrtf(var + 1e-5f);
#pragma unroll
    for (int i = 0; i < 6; i++) {
        int c = lane + 32 * i;
        res_out[(size_t)row * DD + c] = v[i];
        g_h[(size_t)row * DD + c] = (v[i] - mu) * inv * lw[c] + lb[c];
    }
}

// ---------------- TF32 helpers ----------------
__device__ __forceinline__ float to_tf32(float x) {
    uint32_t u;
    asm("cvt.rna.tf32.f32 %0, %1;" : "=r"(u) : "f"(x));
    return __uint_as_float(u);
}

#define MMA_TF32(C0,C1,C2,C3, A0,A1,A2,A3, B0,B1)                               \
    asm volatile("mma.sync.aligned.m16n8k8.row.col.f32.tf32.tf32.f32 "          \
                 "{%0,%1,%2,%3},{%4,%5,%6,%7},{%8,%9},{%0,%1,%2,%3};"           \
                 : "+f"(C0), "+f"(C1), "+f"(C2), "+f"(C3)                       \
                 : "r"(A0), "r"(A1), "r"(A2), "r"(A3), "r"(B0), "r"(B1))

// ---------------- TF32 GEMM: C[M,N] = A[M,K] * W[N,K]^T ----------------
// Requirements: M % 128 == 0, N % 64 == 0, K % 32 == 0.
// TRANSA: A is g_y laid out [b][k][t] with m = b*LL + t (K == DI).
template <bool TRANSA>
__global__ void __launch_bounds__(256) gemm_tf32(const float* __restrict__ A,
                                                 const float* __restrict__ W,
                                                 float* __restrict__ C,
                                                 int M, int N, int K) {
    constexpr int BM = 128, BN = 64, BK = 32;
    // !TRANSA: As(m,k) = AsBuf[m*36 + k]   (128*36 = 4608 floats)
    //  TRANSA: As(m,k) = AsBuf[k*132 + m]  (32*132 = 4224 floats)
    __shared__ float AsBuf[128 * 36];
    __shared__ float WsBuf[64 * 36];

    const int bm = blockIdx.y * BM;
    const int bn = blockIdx.x * BN;
    const int tid = threadIdx.x;
    const int warp = tid >> 5;
    const int lane = tid & 31;
    const int wm = (warp & 3) * 32;     // 4 warps along M
    const int wn = (warp >> 2) * 32;    // 2 warps along N
    const int lq = lane >> 2;           // lane/4
    const int lr = lane & 3;            // lane%4

    float acc[2][4][4];
#pragma unroll
    for (int i = 0; i < 2; i++)
#pragma unroll
        for (int j = 0; j < 4; j++)
#pragma unroll
            for (int c = 0; c < 4; c++) acc[i][j][c] = 0.f;

    for (int k0 = 0; k0 < K; k0 += BK) {
        // ---- load A tile ----
        if (!TRANSA) {
#pragma unroll
            for (int i = tid; i < BM * 8; i += 256) {
                int m = i >> 3, kf = i & 7;
                float4 v = *reinterpret_cast<const float4*>(&A[(size_t)(bm + m) * K + k0 + 4 * kf]);
                AsBuf[m * 36 + 4 * kf + 0] = to_tf32(v.x);
                AsBuf[m * 36 + 4 * kf + 1] = to_tf32(v.y);
                AsBuf[m * 36 + 4 * kf + 2] = to_tf32(v.z);
                AsBuf[m * 36 + 4 * kf + 3] = to_tf32(v.w);
            }
        } else {
            const int b  = bm / LL;
            const int t0 = bm % LL;
            const float* Ab = A + (size_t)b * K * LL + t0;
#pragma unroll
            for (int i = tid; i < BK * 32; i += 256) {
                int k = i >> 5, m4 = i & 31;
                float4 v = *reinterpret_cast<const float4*>(&Ab[(size_t)(k0 + k) * LL + 4 * m4]);
                float4 w;
                w.x = to_tf32(v.x); w.y = to_tf32(v.y);
                w.z = to_tf32(v.z); w.w = to_tf32(v.w);
                *reinterpret_cast<float4*>(&AsBuf[k * 132 + 4 * m4]) = w;
            }
        }
        // ---- load W tile ----
#pragma unroll
        for (int i = tid; i < BN * 8; i += 256) {
            int n = i >> 3, kf = i & 7;
            float4 v = make_float4(0.f, 0.f, 0.f, 0.f);
            if (bn + n < N)
                v = *reinterpret_cast<const float4*>(&W[(size_t)(bn + n) * K + k0 + 4 * kf]);
            WsBuf[n * 36 + 4 * kf + 0] = to_tf32(v.x);
            WsBuf[n * 36 + 4 * kf + 1] = to_tf32(v.y);
            WsBuf[n * 36 + 4 * kf + 2] = to_tf32(v.z);
            WsBuf[n * 36 + 4 * kf + 3] = to_tf32(v.w);
        }
        __syncthreads();

        // ---- compute ----
#pragma unroll
        for (int kk = 0; kk < BK; kk += 8) {
            uint32_t a[2][4], bf[4][2];
#pragma unroll
            for (int mi = 0; mi < 2; mi++) {
                int r0 = wm + mi * 16 + lq;
                if (!TRANSA) {
                    a[mi][0] = __float_as_uint(AsBuf[(r0)     * 36 + kk + lr]);
                    a[mi][1] = __float_as_uint(AsBuf[(r0 + 8) * 36 + kk + lr]);
                    a[mi][2] = __float_as_uint(AsBuf[(r0)     * 36 + kk + 4 + lr]);
                    a[mi][3] = __float_as_uint(AsBuf[(r0 + 8) * 36 + kk + 4 + lr]);
                } else {
                    a[mi][0] = __float_as_uint(AsBuf[(kk + lr)     * 132 + r0]);
                    a[mi][1] = __float_as_uint(AsBuf[(kk + lr)     * 132 + r0 + 8]);
                    a[mi][2] = __float_as_uint(AsBuf[(kk + 4 + lr) * 132 + r0]);
                    a[mi][3] = __float_as_uint(AsBuf[(kk + 4 + lr) * 132 + r0 + 8]);
                }
            }
#pragma unroll
            for (int ni = 0; ni < 4; ni++) {
                int c0 = wn + ni * 8 + lq;
                bf[ni][0] = __float_as_uint(WsBuf[c0 * 36 + kk + lr]);
                bf[ni][1] = __float_as_uint(WsBuf[c0 * 36 + kk + 4 + lr]);
            }
#pragma unroll
            for (int mi = 0; mi < 2; mi++)
#pragma unroll
                for (int ni = 0; ni < 4; ni++)
                    MMA_TF32(acc[mi][ni][0], acc[mi][ni][1], acc[mi][ni][2], acc[mi][ni][3],
                             a[mi][0], a[mi][1], a[mi][2], a[mi][3], bf[ni][0], bf[ni][1]);
        }
        __syncthreads();
    }

    // ---- epilogue (N % 64 == 0 for all uses: no column guards) ----
#pragma unroll
    for (int mi = 0; mi < 2; mi++) {
#pragma unroll
        for (int ni = 0; ni < 4; ni++) {
            int r = bm + wm + mi * 16 + lq;
            int c = bn + wn + ni * 8 + 2 * lr;
            *reinterpret_cast<float2*>(&C[(size_t)r * N + c]) =
                make_float2(acc[mi][ni][0], acc[mi][ni][1]);
            *reinterpret_cast<float2*>(&C[(size_t)(r + 8) * N + c]) =
                make_float2(acc[mi][ni][2], acc[mi][ni][3]);
        }
    }
}

// ---------------- fp32 SIMT GEMM (kept for the small, precision-sensitive xproj) ----------------
template <int BM, int BN, int BK, int TM, int TN>
__global__ void gemm_nt(const float* __restrict__ A, const float* __restrict__ W,
                        float* __restrict__ C, int M, int N, int K) {
    __shared__ float As[BK][BM + 1];
    __shared__ float Ws[BK][BN + 1];
    const int bm = blockIdx.y * BM;
    const int bn = blockIdx.x * BN;
    const int tid = threadIdx.x;
    const int tx = tid % (BN / TN);
    const int ty = tid / (BN / TN);
    float acc[TM][TN];
#pragma unroll
    for (int i = 0; i < TM; i++)
#pragma unroll
        for (int j = 0; j < TN; j++) acc[i][j] = 0.f;

    for (int k0 = 0; k0 < K; k0 += BK) {
#pragma unroll
        for (int i = tid; i < BM * BK; i += 256) {
            int m = i / BK, k = i % BK;
            As[k][m] = A[(size_t)(bm + m) * K + k0 + k];
        }
#pragma unroll
        for (int i = tid; i < BN * BK; i += 256) {
            int n = i / BK, k = i % BK;
            float v = 0.f;
            if (bn + n < N) v = W[(size_t)(bn + n) * K + k0 + k];
            Ws[k][n] = v;
        }
        __syncthreads();
#pragma unroll
        for (int k = 0; k < BK; ++k) {
            float a[TM], w[TN];
#pragma unroll
            for (int i = 0; i < TM; i++) a[i] = As[k][ty * TM + i];
#pragma unroll
            for (int j = 0; j < TN; j++) w[j] = Ws[k][tx * TN + j];
#pragma unroll
            for (int i = 0; i < TM; i++)
#pragma unroll
                for (int j = 0; j < TN; j++) acc[i][j] = fmaf(a[i], w[j], acc[i][j]);
        }
        __syncthreads();
    }
#pragma unroll
    for (int i = 0; i < TM; i++) {
        int m = bm + ty * TM + i;
#pragma unroll
        for (int j = 0; j < TN; j++) {
            int n = bn + tx * TN + j;
            if (n < N) C[(size_t)m * N + n] = acc[i][j];
        }
    }
}

// ---------------- depthwise causal conv (k=4) + SiLU, 4 timesteps/thread ----------------
__global__ void conv_kernel(const float* __restrict__ conv_w, const float* __restrict__ conv_b) {
    int idx = blockIdx.x * blockDim.x + threadIdx.x;   // BL/4 * DI threads
    if (idx >= (BL / 4) * DI) return;
    int d   = idx % DI;
    int blk = idx / DI;
    int t0  = (blk % (LL / 4)) * 4;
    int b   = blk / (LL / 4);
    size_t bl0 = (size_t)b * LL + t0;
    const float* xcol = g_xz + bl0 * (2 * DI) + d;
    float w0 = conv_w[d * 4 + 0], w1 = conv_w[d * 4 + 1];
    float w2 = conv_w[d * 4 + 2], w3 = conv_w[d * 4 + 3];
    float bias = conv_b[d];
    float v[7];
#pragma unroll
    for (int k = -3; k <= 3; k++) {
        int t = t0 + k;
        v[k + 3] = (t >= 0) ? xcol[k * (2 * DI)] : 0.f;
    }
#pragma unroll
    for (int j = 0; j < 4; j++) {
        float acc = bias;
        acc = fmaf(w0, v[j],     acc);
        acc = fmaf(w1, v[j + 1], acc);
        acc = fmaf(w2, v[j + 2], acc);
        acc = fmaf(w3, v[j + 3], acc);
        float s = acc / (1.f + expf(-acc));
        g_xconv[(bl0 + j) * DI + d] = s;
    }
}

// ---------------- dt projection + softplus + pack float4; also emits G = C*B ----------------
__global__ void dtpack_kernel(const float* __restrict__ W_dt, const float* __restrict__ b_dt,
                              const float* __restrict__ D_skip, const float* __restrict__ Cf) {
    int bl = blockIdx.x;          // 0..BL-1
    int d  = threadIdx.x;         // 0..383
    __shared__ float sx[DR];
    if (d < DR) sx[d] = g_xdb[(size_t)bl * NXDB + d];
    // threads 0..63 also fold C into the B-matrix for this row
    if (d < DS) g_G[(size_t)bl * DS + d] = g_xdb[(size_t)bl * NXDB + DR + d] * Cf[d];
    __syncthreads();
    float acc = b_dt[d];
#pragma unroll
    for (int r = 0; r < DR; r++) acc = fmaf(sx[r], W_dt[d * DR + r], acc);
    float dt = fmaxf(acc, 0.f) + log1pf(expf(-fabsf(acc)));
    float xc = g_xconv[(size_t)bl * DI + d];
    float z  = g_xz[(size_t)bl * (2 * DI) + DI + d];
    float sz = z / (1.f + expf(-z));
    int b = bl / LL, l = bl % LL;
    g_P[((size_t)(b * DI + d)) * LL + l] = make_float4(dt, dt * xc, xc * D_skip[d], sz);
}

// ---------------- selective scan: warp per (b,d), deferred smem reduction ----------------
// Per step each lane stores its partial s = h1+h2 to smem (no cross-lane dep in hot
// loop). Every 32 steps the warp transposes-and-reduces the 32x32 tile and writes 32
// coalesced y values. exp(dt*A) computed as ex2(k*dt), k = A*log2(e) precomputed.
__global__ void __launch_bounds__(128) scan_kernel() {
    __shared__ float sred[4][32][33];
    const int wib  = threadIdx.x >> 5;
    const int warp = blockIdx.x * 4 + wib;
    const int lane = threadIdx.x & 31;
    const int b = warp / DI;
    const int d = warp % DI;

    const float4* __restrict__ p  = g_P + (size_t)warp * LL;
    const float2* __restrict__ Gp = reinterpret_cast<const float2*>(g_G + (size_t)b * LL * DS) + lane;
    float* __restrict__ yp = g_y + (size_t)warp * LL;   // transposed [b][d][t]

    const float k1 = g_A[d * DS + 2 * lane]     * 1.44269504f;
    const float k2 = g_A[d * DS + 2 * lane + 1] * 1.44269504f;

    float h1 = 0.f, h2 = 0.f;
    float4 pk = p[0];
    float2 gv = Gp[0];
    float (*row)[33] = sred[wib];

    for (int t0 = 0; t0 < LL; t0 += 32) {
#pragma unroll 8
        for (int j = 0; j < 32; ++j) {
            const int t = t0 + j;
            float4 pk_n = pk;
            float2 gv_n = gv;
            if (t + 1 < LL) {
                pk_n = p[t + 1];
                gv_n = Gp[(size_t)(t + 1) * (DS / 2)];
            }
            float e1, e2;
            asm("ex2.approx.f32 %0, %1;" : "=f"(e1) : "f"(k1 * pk.x));
            asm("ex2.approx.f32 %0, %1;" : "=f"(e2) : "f"(k2 * pk.x));
            h1 = fmaf(e1, h1, pk.y * gv.x);
            h2 = fmaf(e2, h2, pk.y * gv.y);
            row[j][lane] = h1 + h2;
            pk = pk_n;
            gv = gv_n;
        }
        __syncwarp();
        // lane j sums row j (all lanes' partials for step t0+j); 4-way ILP
        float s0 = 0.f, s1 = 0.f, s2 = 0.f, s3 = 0.f;
#pragma unroll
        for (int i = 0; i < 32; i += 4) {
            s0 += row[lane][i + 0];
            s1 += row[lane][i + 1];
            s2 += row[lane][i + 2];
            s3 += row[lane][i + 3];
        }
        float4 q = p[t0 + lane];            // z,w scalars for step t0+lane (L1 hit)
        yp[t0 + lane] = ((s0 + s1) + (s2 + s3) + q.z) * q.w;
        __syncwarp();
    }
}

// ---------------- launch ----------------
extern "C" void kernel_launch(void* const* d_in, const int* in_sizes, int n_in,
                              void* d_out, int out_size) {
    const float* hidden  = (const float*)d_in[0];
    const float* resid   = (const float*)d_in[1];
    const float* ln_w    = (const float*)d_in[2];
    const float* ln_b    = (const float*)d_in[3];
    const float* W_in    = (const float*)d_in[4];
    const float* conv_w  = (const float*)d_in[5];
    const float* conv_b  = (const float*)d_in[6];
    const float* W_xproj = (const float*)d_in[7];
    const float* W_dt    = (const float*)d_in[8];
    const float* b_dt    = (const float*)d_in[9];
    const float* A_log   = (const float*)d_in[10];
    const float* D_skip  = (const float*)d_in[11];
    const float* C_fixed = (const float*)d_in[12];
    const float* W_out   = (const float*)d_in[13];

    float* out     = (float*)d_out;                    // (B,L,D)
    float* res_out = (float*)d_out + (size_t)BL * DD;  // (B,L,D)

    float* d_h;   cudaGetSymbolAddress((void**)&d_h,   g_h);
    float* d_xz;  cudaGetSymbolAddress((void**)&d_xz,  g_xz);
    float* d_xc;  cudaGetSymbolAddress((void**)&d_xc,  g_xconv);
    float* d_xdb; cudaGetSymbolAddress((void**)&d_xdb, g_xdb);
    float* d_y;   cudaGetSymbolAddress((void**)&d_y,   g_y);

    // 0) A = -exp(A_log)
    prep_A_kernel<<<(DI * DS + 255) / 256, 256>>>(A_log);

    // 1) residual add + LN
    ln_kernel<<<BL / 8, 256>>>(hidden, resid, ln_w, ln_b, res_out);

    // 2) xz = h @ W_in^T   (M=8192, N=768, K=192) — TF32
    {
        dim3 grid(768 / 64, BL / 128);
        gemm_tf32<false><<<grid, 256>>>(d_h, W_in, d_xz, BL, 2 * DI, DD);
    }

    // 3) depthwise causal conv + silu (4 t/thread)
    conv_kernel<<<((BL / 4) * DI + 255) / 256, 256>>>(conv_w, conv_b);

    // 4) xdb = xconv @ W_xproj^T  (M=8192, N=76, K=384) — fp32 (feeds exp path)
    {
        dim3 grid((NXDB + 63) / 64, BL / 128);
        gemm_nt<128, 64, 16, 8, 4><<<grid, 256>>>(d_xc, W_xproj, d_xdb, BL, NXDB, DI);
    }

    // 5+6) G = C*B fused into dt / pack
    dtpack_kernel<<<BL, DI>>>(W_dt, b_dt, D_skip, C_fixed);

    // 7) scan
    scan_kernel<<<(BB * DI) / 4, 128>>>();

    // 8) out = y^T @ W_out^T  (M=8192, N=192, K=384) — TF32, transposed A
    {
        dim3 grid(DD / 64, BL / 128);
        gemm_tf32<true><<<grid, 256>>>(d_y, W_out, out, BL, DD, DI);
    }
}

// round 12
// speedup vs baseline: 2.1836x; 1.4594x over previous
#include <cuda_runtime.h>
#include <math.h>
#include <stdint.h>

// ---------------- problem constants ----------------
#define BB 4
#define LL 2048
#define DD 192
#define DI 384
#define DS 64
#define DR 12
#define NXDB (DR + DS)      // 76
#define BL (BB * LL)        // 8192

// ---------------- scratch (static device globals; no allocation) ----------------
__device__ float  g_h[(size_t)BL * DD];            // LN output
__device__ float  g_xz[(size_t)BL * 2 * DI];       // x | z
__device__ float  g_xconv[(size_t)BL * DI];        // conv+silu output (u)
__device__ float  g_xdb[(size_t)BL * NXDB];        // [dt_rank | B-matrix]
__device__ float  g_G[(size_t)BL * DS];            // C_n * B[b,t,n]
__device__ float4 g_P[(size_t)BB * DI * LL];       // packed (dt, dt*u, u*D, silu(z)), (b,d,t)
__device__ float  g_y[(size_t)BB * DI * LL];       // scan output, TRANSPOSED [b][d][t]
__device__ float  g_A[DI * DS];                    // A = -exp(A_log)

// ---------------- kernel 0: A = -exp(A_log) ----------------
__global__ void prep_A_kernel(const float* __restrict__ A_log) {
    int i = blockIdx.x * blockDim.x + threadIdx.x;
    if (i < DI * DS) g_A[i] = -expf(A_log[i]);
}

// ---------------- kernel 1: residual += hidden; LayerNorm -> h ----------------
__global__ void ln_kernel(const float* __restrict__ hid, const float* __restrict__ res,
                          const float* __restrict__ lw, const float* __restrict__ lb,
                          float* __restrict__ res_out) {
    int row  = blockIdx.x * (blockDim.x >> 5) + (threadIdx.x >> 5);
    int lane = threadIdx.x & 31;
    if (row >= BL) return;
    const float* hr = hid + (size_t)row * DD;
    const float* rr = res + (size_t)row * DD;
    float v[6];
    float sum = 0.f, sq = 0.f;
#pragma unroll
    for (int i = 0; i < 6; i++) {
        v[i] = hr[lane + 32 * i] + rr[lane + 32 * i];
        sum += v[i];
        sq  = fmaf(v[i], v[i], sq);
    }
#pragma unroll
    for (int m = 16; m >= 1; m >>= 1) {
        sum += __shfl_xor_sync(0xffffffffu, sum, m);
        sq  += __shfl_xor_sync(0xffffffffu, sq,  m);
    }
    float mu  = sum * (1.f / DD);
    float var = sq * (1.f / DD) - mu * mu;
    float inv = rsqrtf(var + 1e-5f);
#pragma unroll
    for (int i = 0; i < 6; i++) {
        int c = lane + 32 * i;
        res_out[(size_t)row * DD + c] = v[i];
        g_h[(size_t)row * DD + c] = (v[i] - mu) * inv * lw[c] + lb[c];
    }
}

// ---------------- TF32 helpers ----------------
__device__ __forceinline__ float to_tf32(float x) {
    uint32_t u;
    asm("cvt.rna.tf32.f32 %0, %1;" : "=r"(u) : "f"(x));
    return __uint_as_float(u);
}

#define MMA_TF32(C0,C1,C2,C3, A0,A1,A2,A3, B0,B1)                               \
    asm volatile("mma.sync.aligned.m16n8k8.row.col.f32.tf32.tf32.f32 "          \
                 "{%0,%1,%2,%3},{%4,%5,%6,%7},{%8,%9},{%0,%1,%2,%3};"           \
                 : "+f"(C0), "+f"(C1), "+f"(C2), "+f"(C3)                       \
                 : "r"(A0), "r"(A1), "r"(A2), "r"(A3), "r"(B0), "r"(B1))

// ---------------- TF32 GEMM: C[M,N] = A[M,K] * W[N,K]^T ----------------
// Requirements: M % 128 == 0, N % 64 == 0, K % 32 == 0.
// TRANSA: A is g_y laid out [b][k][t] with m = b*LL + t (K == DI).
template <bool TRANSA>
__global__ void __launch_bounds__(256) gemm_tf32(const float* __restrict__ A,
                                                 const float* __restrict__ W,
                                                 float* __restrict__ C,
                                                 int M, int N, int K) {
    constexpr int BM = 128, BN = 64, BK = 32;
    __shared__ float AsBuf[128 * 36];
    __shared__ float WsBuf[64 * 36];

    const int bm = blockIdx.y * BM;
    const int bn = blockIdx.x * BN;
    const int tid = threadIdx.x;
    const int warp = tid >> 5;
    const int lane = tid & 31;
    const int wm = (warp & 3) * 32;     // 4 warps along M
    const int wn = (warp >> 2) * 32;    // 2 warps along N
    const int lq = lane >> 2;           // lane/4
    const int lr = lane & 3;            // lane%4

    float acc[2][4][4];
#pragma unroll
    for (int i = 0; i < 2; i++)
#pragma unroll
        for (int j = 0; j < 4; j++)
#pragma unroll
            for (int c = 0; c < 4; c++) acc[i][j][c] = 0.f;

    for (int k0 = 0; k0 < K; k0 += BK) {
        // ---- load A tile ----
        if (!TRANSA) {
#pragma unroll
            for (int i = tid; i < BM * 8; i += 256) {
                int m = i >> 3, kf = i & 7;
                float4 v = *reinterpret_cast<const float4*>(&A[(size_t)(bm + m) * K + k0 + 4 * kf]);
                AsBuf[m * 36 + 4 * kf + 0] = to_tf32(v.x);
                AsBuf[m * 36 + 4 * kf + 1] = to_tf32(v.y);
                AsBuf[m * 36 + 4 * kf + 2] = to_tf32(v.z);
                AsBuf[m * 36 + 4 * kf + 3] = to_tf32(v.w);
            }
        } else {
            const int b  = bm / LL;
            const int t0 = bm % LL;
            const float* Ab = A + (size_t)b * K * LL + t0;
#pragma unroll
            for (int i = tid; i < BK * 32; i += 256) {
                int k = i >> 5, m4 = i & 31;
                float4 v = *reinterpret_cast<const float4*>(&Ab[(size_t)(k0 + k) * LL + 4 * m4]);
                float4 w;
                w.x = to_tf32(v.x); w.y = to_tf32(v.y);
                w.z = to_tf32(v.z); w.w = to_tf32(v.w);
                *reinterpret_cast<float4*>(&AsBuf[k * 132 + 4 * m4]) = w;
            }
        }
        // ---- load W tile ----
#pragma unroll
        for (int i = tid; i < BN * 8; i += 256) {
            int n = i >> 3, kf = i & 7;
            float4 v = make_float4(0.f, 0.f, 0.f, 0.f);
            if (bn + n < N)
                v = *reinterpret_cast<const float4*>(&W[(size_t)(bn + n) * K + k0 + 4 * kf]);
            WsBuf[n * 36 + 4 * kf + 0] = to_tf32(v.x);
            WsBuf[n * 36 + 4 * kf + 1] = to_tf32(v.y);
            WsBuf[n * 36 + 4 * kf + 2] = to_tf32(v.z);
            WsBuf[n * 36 + 4 * kf + 3] = to_tf32(v.w);
        }
        __syncthreads();

        // ---- compute ----
#pragma unroll
        for (int kk = 0; kk < BK; kk += 8) {
            uint32_t a[2][4], bf[4][2];
#pragma unroll
            for (int mi = 0; mi < 2; mi++) {
                int r0 = wm + mi * 16 + lq;
                if (!TRANSA) {
                    a[mi][0] = __float_as_uint(AsBuf[(r0)     * 36 + kk + lr]);
                    a[mi][1] = __float_as_uint(AsBuf[(r0 + 8) * 36 + kk + lr]);
                    a[mi][2] = __float_as_uint(AsBuf[(r0)     * 36 + kk + 4 + lr]);
                    a[mi][3] = __float_as_uint(AsBuf[(r0 + 8) * 36 + kk + 4 + lr]);
                } else {
                    a[mi][0] = __float_as_uint(AsBuf[(kk + lr)     * 132 + r0]);
                    a[mi][1] = __float_as_uint(AsBuf[(kk + lr)     * 132 + r0 + 8]);
                    a[mi][2] = __float_as_uint(AsBuf[(kk + 4 + lr) * 132 + r0]);
                    a[mi][3] = __float_as_uint(AsBuf[(kk + 4 + lr) * 132 + r0 + 8]);
                }
            }
#pragma unroll
            for (int ni = 0; ni < 4; ni++) {
                int c0 = wn + ni * 8 + lq;
                bf[ni][0] = __float_as_uint(WsBuf[c0 * 36 + kk + lr]);
                bf[ni][1] = __float_as_uint(WsBuf[c0 * 36 + kk + 4 + lr]);
            }
#pragma unroll
            for (int mi = 0; mi < 2; mi++)
#pragma unroll
                for (int ni = 0; ni < 4; ni++)
                    MMA_TF32(acc[mi][ni][0], acc[mi][ni][1], acc[mi][ni][2], acc[mi][ni][3],
                             a[mi][0], a[mi][1], a[mi][2], a[mi][3], bf[ni][0], bf[ni][1]);
        }
        __syncthreads();
    }

    // ---- epilogue ----
#pragma unroll
    for (int mi = 0; mi < 2; mi++) {
#pragma unroll
        for (int ni = 0; ni < 4; ni++) {
            int r = bm + wm + mi * 16 + lq;
            int c = bn + wn + ni * 8 + 2 * lr;
            *reinterpret_cast<float2*>(&C[(size_t)r * N + c]) =
                make_float2(acc[mi][ni][0], acc[mi][ni][1]);
            *reinterpret_cast<float2*>(&C[(size_t)(r + 8) * N + c]) =
                make_float2(acc[mi][ni][2], acc[mi][ni][3]);
        }
    }
}

// ---------------- fp32 SIMT GEMM (precision-sensitive xproj) ----------------
template <int BM, int BN, int BK, int TM, int TN>
__global__ void gemm_nt(const float* __restrict__ A, const float* __restrict__ W,
                        float* __restrict__ C, int M, int N, int K) {
    __shared__ float As[BK][BM + 1];
    __shared__ float Ws[BK][BN + 1];
    const int bm = blockIdx.y * BM;
    const int bn = blockIdx.x * BN;
    const int tid = threadIdx.x;
    const int tx = tid % (BN / TN);
    const int ty = tid / (BN / TN);
    float acc[TM][TN];
#pragma unroll
    for (int i = 0; i < TM; i++)
#pragma unroll
        for (int j = 0; j < TN; j++) acc[i][j] = 0.f;

    for (int k0 = 0; k0 < K; k0 += BK) {
#pragma unroll
        for (int i = tid; i < BM * BK; i += 256) {
            int m = i / BK, k = i % BK;
            As[k][m] = A[(size_t)(bm + m) * K + k0 + k];
        }
#pragma unroll
        for (int i = tid; i < BN * BK; i += 256) {
            int n = i / BK, k = i % BK;
            float v = 0.f;
            if (bn + n < N) v = W[(size_t)(bn + n) * K + k0 + k];
            Ws[k][n] = v;
        }
        __syncthreads();
#pragma unroll
        for (int k = 0; k < BK; ++k) {
            float a[TM], w[TN];
#pragma unroll
            for (int i = 0; i < TM; i++) a[i] = As[k][ty * TM + i];
#pragma unroll
            for (int j = 0; j < TN; j++) w[j] = Ws[k][tx * TN + j];
#pragma unroll
            for (int i = 0; i < TM; i++)
#pragma unroll
                for (int j = 0; j < TN; j++) acc[i][j] = fmaf(a[i], w[j], acc[i][j]);
        }
        __syncthreads();
    }
#pragma unroll
    for (int i = 0; i < TM; i++) {
        int m = bm + ty * TM + i;
#pragma unroll
        for (int j = 0; j < TN; j++) {
            int n = bn + tx * TN + j;
            if (n < N) C[(size_t)m * N + n] = acc[i][j];
        }
    }
}

// ---------------- depthwise causal conv (k=4) + SiLU, 4 timesteps/thread ----------------
__global__ void conv_kernel(const float* __restrict__ conv_w, const float* __restrict__ conv_b) {
    int idx = blockIdx.x * blockDim.x + threadIdx.x;   // BL/4 * DI threads
    if (idx >= (BL / 4) * DI) return;
    int d   = idx % DI;
    int blk = idx / DI;
    int t0  = (blk % (LL / 4)) * 4;
    int b   = blk / (LL / 4);
    size_t bl0 = (size_t)b * LL + t0;
    const float* xcol = g_xz + bl0 * (2 * DI) + d;
    float w0 = conv_w[d * 4 + 0], w1 = conv_w[d * 4 + 1];
    float w2 = conv_w[d * 4 + 2], w3 = conv_w[d * 4 + 3];
    float bias = conv_b[d];
    float v[7];
#pragma unroll
    for (int k = -3; k <= 3; k++) {
        int t = t0 + k;
        v[k + 3] = (t >= 0) ? xcol[k * (2 * DI)] : 0.f;
    }
#pragma unroll
    for (int j = 0; j < 4; j++) {
        float acc = bias;
        acc = fmaf(w0, v[j],     acc);
        acc = fmaf(w1, v[j + 1], acc);
        acc = fmaf(w2, v[j + 2], acc);
        acc = fmaf(w3, v[j + 3], acc);
        // silu via fast intrinsics (MUFU): error ~1e-6, invisible under tf32 floor
        float s = __fdividef(acc, 1.f + __expf(-acc));
        g_xconv[(bl0 + j) * DI + d] = s;
    }
}

// ---------------- dt projection + softplus + pack float4; also emits G = C*B ----------------
__global__ void dtpack_kernel(const float* __restrict__ W_dt, const float* __restrict__ b_dt,
                              const float* __restrict__ D_skip, const float* __restrict__ Cf) {
    int bl = blockIdx.x;          // 0..BL-1
    int d  = threadIdx.x;         // 0..383
    __shared__ float sx[DR];
    if (d < DR) sx[d] = g_xdb[(size_t)bl * NXDB + d];
    // threads 0..63 also fold C into the B-matrix for this row
    if (d < DS) g_G[(size_t)bl * DS + d] = g_xdb[(size_t)bl * NXDB + DR + d] * Cf[d];
    __syncthreads();
    float acc = b_dt[d];
#pragma unroll
    for (int r = 0; r < DR; r++) acc = fmaf(sx[r], W_dt[d * DR + r], acc);
    // softplus via fast intrinsics (stable form)
    float dt = fmaxf(acc, 0.f) + __logf(1.f + __expf(-fabsf(acc)));
    float xc = g_xconv[(size_t)bl * DI + d];
    float z  = g_xz[(size_t)bl * (2 * DI) + DI + d];
    float sz = __fdividef(z, 1.f + __expf(-z));
    int b = bl / LL, l = bl % LL;
    g_P[((size_t)(b * DI + d)) * LL + l] = make_float4(dt, dt * xc, xc * D_skip[d], sz);
}

// ---------------- selective scan: warp per (b,d), G staged in smem ----------------
// All 4 warps of a block share the same batch b (warp id is d-major), so the G
// stream is loaded into smem ONCE per block per 32-step chunk (4x L2-traffic cut).
// Per step each lane stores its partial s = h1+h2 to sred; every 32 steps the warp
// transposes-and-reduces and writes 32 coalesced y values.
__global__ void __launch_bounds__(128) scan_kernel() {
    __shared__ float sG[32][64];          // 8 KB: G[t0..t0+31][0..63] for this block's b
    __shared__ float sred[4][32][33];
    const int wib  = threadIdx.x >> 5;
    const int warp = blockIdx.x * 4 + wib;
    const int lane = threadIdx.x & 31;
    const int b = warp / DI;
    const int d = warp % DI;

    const float4* __restrict__ p    = g_P + (size_t)warp * LL;
    const float*  __restrict__ Gsrc = g_G + (size_t)b * LL * DS;
    float* __restrict__ yp = g_y + (size_t)warp * LL;   // transposed [b][d][t]

    const float k1 = g_A[d * DS + 2 * lane]     * 1.44269504f;
    const float k2 = g_A[d * DS + 2 * lane + 1] * 1.44269504f;

    float h1 = 0.f, h2 = 0.f;
    float4 pk = p[0];
    float (*row)[33] = sred[wib];

    for (int t0 = 0; t0 < LL; t0 += 32) {
        __syncthreads();   // all warps done reading previous chunk's sG
        {
            // cooperative load of G[t0..t0+31][*]: 2048 floats = 512 float4
            const float4* gs4 = reinterpret_cast<const float4*>(Gsrc + (size_t)t0 * DS);
            float4* sg4 = reinterpret_cast<float4*>(&sG[0][0]);
            sg4[threadIdx.x]       = gs4[threadIdx.x];
            sg4[threadIdx.x + 128] = gs4[threadIdx.x + 128];
            sg4[threadIdx.x + 256] = gs4[threadIdx.x + 256];
            sg4[threadIdx.x + 384] = gs4[threadIdx.x + 384];
        }
        __syncthreads();

        float2 gv = *reinterpret_cast<const float2*>(&sG[0][2 * lane]);
#pragma unroll 8
        for (int j = 0; j < 32; ++j) {
            float4 pk_n = pk;
            float2 gv_n = gv;
            if (j < 31)
                gv_n = *reinterpret_cast<const float2*>(&sG[j + 1][2 * lane]);
            if (t0 + j + 1 < LL)
                pk_n = p[t0 + j + 1];
            float e1, e2;
            asm("ex2.approx.f32 %0, %1;" : "=f"(e1) : "f"(k1 * pk.x));
            asm("ex2.approx.f32 %0, %1;" : "=f"(e2) : "f"(k2 * pk.x));
            h1 = fmaf(e1, h1, pk.y * gv.x);
            h2 = fmaf(e2, h2, pk.y * gv.y);
            row[j][lane] = h1 + h2;
            pk = pk_n;
            gv = gv_n;
        }
        __syncwarp();
        // lane j sums row j (all lanes' partials for step t0+j); 4-way ILP
        float s0 = 0.f, s1 = 0.f, s2 = 0.f, s3 = 0.f;
#pragma unroll
        for (int i = 0; i < 32; i += 4) {
            s0 += row[lane][i + 0];
            s1 += row[lane][i + 1];
            s2 += row[lane][i + 2];
            s3 += row[lane][i + 3];
        }
        float4 q = p[t0 + lane];            // z,w scalars for step t0+lane (L1 hit)
        yp[t0 + lane] = ((s0 + s1) + (s2 + s3) + q.z) * q.w;
        __syncwarp();
    }
}

// ---------------- launch ----------------
extern "C" void kernel_launch(void* const* d_in, const int* in_sizes, int n_in,
                              void* d_out, int out_size) {
    const float* hidden  = (const float*)d_in[0];
    const float* resid   = (const float*)d_in[1];
    const float* ln_w    = (const float*)d_in[2];
    const float* ln_b    = (const float*)d_in[3];
    const float* W_in    = (const float*)d_in[4];
    const float* conv_w  = (const float*)d_in[5];
    const float* conv_b  = (const float*)d_in[6];
    const float* W_xproj = (const float*)d_in[7];
    const float* W_dt    = (const float*)d_in[8];
    const float* b_dt    = (const float*)d_in[9];
    const float* A_log   = (const float*)d_in[10];
    const float* D_skip  = (const float*)d_in[11];
    const float* C_fixed = (const float*)d_in[12];
    const float* W_out   = (const float*)d_in[13];

    float* out     = (float*)d_out;                    // (B,L,D)
    float* res_out = (float*)d_out + (size_t)BL * DD;  // (B,L,D)

    float* d_h;   cudaGetSymbolAddress((void**)&d_h,   g_h);
    float* d_xz;  cudaGetSymbolAddress((void**)&d_xz,  g_xz);
    float* d_xc;  cudaGetSymbolAddress((void**)&d_xc,  g_xconv);
    float* d_xdb; cudaGetSymbolAddress((void**)&d_xdb, g_xdb);
    float* d_y;   cudaGetSymbolAddress((void**)&d_y,   g_y);

    // 0) A = -exp(A_log)
    prep_A_kernel<<<(DI * DS + 255) / 256, 256>>>(A_log);

    // 1) residual add + LN
    ln_kernel<<<BL / 8, 256>>>(hidden, resid, ln_w, ln_b, res_out);

    // 2) xz = h @ W_in^T   (M=8192, N=768, K=192) — TF32
    {
        dim3 grid(768 / 64, BL / 128);
        gemm_tf32<false><<<grid, 256>>>(d_h, W_in, d_xz, BL, 2 * DI, DD);
    }

    // 3) depthwise causal conv + silu (4 t/thread)
    conv_kernel<<<((BL / 4) * DI + 255) / 256, 256>>>(conv_w, conv_b);

    // 4) xdb = xconv @ W_xproj^T  (M=8192, N=76, K=384) — fp32 (feeds exp path)
    {
        dim3 grid((NXDB + 63) / 64, BL / 128);
        gemm_nt<128, 64, 16, 8, 4><<<grid, 256>>>(d_xc, W_xproj, d_xdb, BL, NXDB, DI);
    }

    // 5+6) G = C*B fused into dt / pack
    dtpack_kernel<<<BL, DI>>>(W_dt, b_dt, D_skip, C_fixed);

    // 7) scan
    scan_kernel<<<(BB * DI) / 4, 128>>>();

    // 8) out = y^T @ W_out^T  (M=8192, N=192, K=384) — TF32, transposed A
    {
        dim3 grid(DD / 64, BL / 128);
        gemm_tf32<true><<<grid, 256>>>(d_y, W_out, out, BL, DD, DI);
    }
}

// round 15
// speedup vs baseline: 2.1845x; 1.0004x over previous
#include <cuda_runtime.h>
#include <math.h>
#include <stdint.h>

// ---------------- problem constants ----------------
#define BB 4
#define LL 2048
#define DD 192
#define DI 384
#define DS 64
#define DR 12
#define NXDB (DR + DS)      // 76
#define BL (BB * LL)        // 8192

// ---------------- scratch (static device globals; no allocation) ----------------
__device__ float  g_h[(size_t)BL * DD];            // LN output
__device__ float  g_xz[(size_t)BL * 2 * DI];       // x | z
__device__ float  g_xconv[(size_t)BL * DI];        // conv+silu output (u)
__device__ float  g_xdb[(size_t)BL * NXDB];        // [dt_rank | B-matrix]
__device__ float  g_G[(size_t)BL * DS];            // C_n * B[b,t,n]
__device__ float4 g_P[(size_t)BB * DI * LL];       // packed (dt, dt*u, u*D, silu(z)), (b,d,t)
__device__ float  g_y[(size_t)BB * DI * LL];       // scan output, TRANSPOSED [b][d][t]
__device__ float  g_A[DI * DS];                    // A = -exp(A_log)

// ---------------- kernel 0: A = -exp(A_log) ----------------
__global__ void prep_A_kernel(const float* __restrict__ A_log) {
    int i = blockIdx.x * blockDim.x + threadIdx.x;
    if (i < DI * DS) g_A[i] = -expf(A_log[i]);
}

// ---------------- kernel 1: residual += hidden; LayerNorm -> h ----------------
__global__ void ln_kernel(const float* __restrict__ hid, const float* __restrict__ res,
                          const float* __restrict__ lw, const float* __restrict__ lb,
                          float* __restrict__ res_out) {
    int row  = blockIdx.x * (blockDim.x >> 5) + (threadIdx.x >> 5);
    int lane = threadIdx.x & 31;
    if (row >= BL) return;
    const float* hr = hid + (size_t)row * DD;
    const float* rr = res + (size_t)row * DD;
    float v[6];
    float sum = 0.f, sq = 0.f;
#pragma unroll
    for (int i = 0; i < 6; i++) {
        v[i] = hr[lane + 32 * i] + rr[lane + 32 * i];
        sum += v[i];
        sq  = fmaf(v[i], v[i], sq);
    }
#pragma unroll
    for (int m = 16; m >= 1; m >>= 1) {
        sum += __shfl_xor_sync(0xffffffffu, sum, m);
        sq  += __shfl_xor_sync(0xffffffffu, sq,  m);
    }
    float mu  = sum * (1.f / DD);
    float var = sq * (1.f / DD) - mu * mu;
    float inv = rsqrtf(var + 1e-5f);
#pragma unroll
    for (int i = 0; i < 6; i++) {
        int c = lane + 32 * i;
        res_out[(size_t)row * DD + c] = v[i];
        g_h[(size_t)row * DD + c] = (v[i] - mu) * inv * lw[c] + lb[c];
    }
}

// ---------------- TF32 / cp.async helpers ----------------
__device__ __forceinline__ float to_tf32(float x) {
    uint32_t u;
    asm("cvt.rna.tf32.f32 %0, %1;" : "=r"(u) : "f"(x));
    return __uint_as_float(u);
}

__device__ __forceinline__ void cp_async16(float* smem_dst, const float* gmem_src) {
    uint32_t s = (uint32_t)__cvta_generic_to_shared(smem_dst);
    asm volatile("cp.async.cg.shared.global [%0], [%1], 16;" :: "r"(s), "l"(gmem_src));
}
#define CP_COMMIT() asm volatile("cp.async.commit_group;" ::: "memory")
#define CP_WAIT1()  asm volatile("cp.async.wait_group 1;" ::: "memory")
#define CP_WAIT0()  asm volatile("cp.async.wait_group 0;" ::: "memory")

#define MMA_TF32(C0,C1,C2,C3, A0,A1,A2,A3, B0,B1)                               \
    asm volatile("mma.sync.aligned.m16n8k8.row.col.f32.tf32.tf32.f32 "          \
                 "{%0,%1,%2,%3},{%4,%5,%6,%7},{%8,%9},{%0,%1,%2,%3};"           \
                 : "+f"(C0), "+f"(C1), "+f"(C2), "+f"(C3)                       \
                 : "r"(A0), "r"(A1), "r"(A2), "r"(A3), "r"(B0), "r"(B1))

// ---------------- TF32 GEMM, cp.async double-buffered ----------------
// C[M,N] = A[M,K] * W[N,K]^T.  Requires M%128==0, N%64==0, K%32==0.
// TRANSA: A is g_y laid out [b][k][t] with m = b*LL + t (K == DI).
// tf32 conversion (cvt.rna) applied at LDS-read time (same numerics as before).
template <bool TRANSA>
__global__ void __launch_bounds__(256) gemm_tf32(const float* __restrict__ A,
                                                 const float* __restrict__ W,
                                                 float* __restrict__ C,
                                                 int M, int N, int K) {
    constexpr int BM = 128, BN = 64, BK = 32;
    __shared__ float AsBuf[2][128 * 36];
    __shared__ float WsBuf[2][64 * 36];

    const int bm = blockIdx.y * BM;
    const int bn = blockIdx.x * BN;
    const int tid = threadIdx.x;
    const int warp = tid >> 5;
    const int lane = tid & 31;
    const int wm = (warp & 3) * 32;     // 4 warps along M
    const int wn = (warp >> 2) * 32;    // 2 warps along N
    const int lq = lane >> 2;           // lane/4
    const int lr = lane & 3;            // lane%4

    const int bA = TRANSA ? (bm / LL) : 0;
    const int t0A = TRANSA ? (bm % LL) : 0;
    const float* Ab = TRANSA ? (A + (size_t)bA * K * LL + t0A) : A;

    float acc[2][4][4];
#pragma unroll
    for (int i = 0; i < 2; i++)
#pragma unroll
        for (int j = 0; j < 4; j++)
#pragma unroll
            for (int c = 0; c < 4; c++) acc[i][j][c] = 0.f;

    // ---- stage loader (cp.async, raw fp32 bytes) ----
    auto load_stage = [&](int st, int k0) {
        if (!TRANSA) {
#pragma unroll
            for (int i = tid; i < BM * 8; i += 256) {
                int m = i >> 3, kf = i & 7;
                cp_async16(&AsBuf[st][m * 36 + 4 * kf],
                           &A[(size_t)(bm + m) * K + k0 + 4 * kf]);
            }
        } else {
#pragma unroll
            for (int i = tid; i < BK * 32; i += 256) {
                int k = i >> 5, m4 = i & 31;
                cp_async16(&AsBuf[st][k * 132 + 4 * m4],
                           &Ab[(size_t)(k0 + k) * LL + 4 * m4]);
            }
        }
#pragma unroll
        for (int i = tid; i < BN * 8; i += 256) {
            int n = i >> 3, kf = i & 7;
            cp_async16(&WsBuf[st][n * 36 + 4 * kf],
                       &W[(size_t)(bn + n) * K + k0 + 4 * kf]);
        }
    };

    const int niter = K / BK;
    load_stage(0, 0);
    CP_COMMIT();

    for (int it = 0; it < niter; ++it) {
        const int st = it & 1;
        if (it + 1 < niter) {
            load_stage((it + 1) & 1, (it + 1) * BK);
            CP_COMMIT();
            CP_WAIT1();
        } else {
            CP_WAIT0();
        }
        __syncthreads();

        const float* As = AsBuf[st];
        const float* Ws = WsBuf[st];
#pragma unroll
        for (int kk = 0; kk < BK; kk += 8) {
            uint32_t a[2][4], bf[4][2];
#pragma unroll
            for (int mi = 0; mi < 2; mi++) {
                int r0 = wm + mi * 16 + lq;
                if (!TRANSA) {
                    a[mi][0] = __float_as_uint(to_tf32(As[(r0)     * 36 + kk + lr]));
                    a[mi][1] = __float_as_uint(to_tf32(As[(r0 + 8) * 36 + kk + lr]));
                    a[mi][2] = __float_as_uint(to_tf32(As[(r0)     * 36 + kk + 4 + lr]));
                    a[mi][3] = __float_as_uint(to_tf32(As[(r0 + 8) * 36 + kk + 4 + lr]));
                } else {
                    a[mi][0] = __float_as_uint(to_tf32(As[(kk + lr)     * 132 + r0]));
                    a[mi][1] = __float_as_uint(to_tf32(As[(kk + lr)     * 132 + r0 + 8]));
                    a[mi][2] = __float_as_uint(to_tf32(As[(kk + 4 + lr) * 132 + r0]));
                    a[mi][3] = __float_as_uint(to_tf32(As[(kk + 4 + lr) * 132 + r0 + 8]));
                }
            }
#pragma unroll
            for (int ni = 0; ni < 4; ni++) {
                int c0 = wn + ni * 8 + lq;
                bf[ni][0] = __float_as_uint(to_tf32(Ws[c0 * 36 + kk + lr]));
                bf[ni][1] = __float_as_uint(to_tf32(Ws[c0 * 36 + kk + 4 + lr]));
            }
#pragma unroll
            for (int mi = 0; mi < 2; mi++)
#pragma unroll
                for (int ni = 0; ni < 4; ni++)
                    MMA_TF32(acc[mi][ni][0], acc[mi][ni][1], acc[mi][ni][2], acc[mi][ni][3],
                             a[mi][0], a[mi][1], a[mi][2], a[mi][3], bf[ni][0], bf[ni][1]);
        }
        __syncthreads();
    }

    // ---- epilogue (N % 64 == 0: no column guards) ----
#pragma unroll
    for (int mi = 0; mi < 2; mi++) {
#pragma unroll
        for (int ni = 0; ni < 4; ni++) {
            int r = bm + wm + mi * 16 + lq;
            int c = bn + wn + ni * 8 + 2 * lr;
            *reinterpret_cast<float2*>(&C[(size_t)r * N + c]) =
                make_float2(acc[mi][ni][0], acc[mi][ni][1]);
            *reinterpret_cast<float2*>(&C[(size_t)(r + 8) * N + c]) =
                make_float2(acc[mi][ni][2], acc[mi][ni][3]);
        }
    }
}

// ---------------- fp32 SIMT GEMM (precision-sensitive xproj) ----------------
template <int BM, int BN, int BK, int TM, int TN>
__global__ void gemm_nt(const float* __restrict__ A, const float* __restrict__ W,
                        float* __restrict__ C, int M, int N, int K) {
    __shared__ float As[BK][BM + 1];
    __shared__ float Ws[BK][BN + 1];
    const int bm = blockIdx.y * BM;
    const int bn = blockIdx.x * BN;
    const int tid = threadIdx.x;
    const int tx = tid % (BN / TN);
    const int ty = tid / (BN / TN);
    float acc[TM][TN];
#pragma unroll
    for (int i = 0; i < TM; i++)
#pragma unroll
        for (int j = 0; j < TN; j++) acc[i][j] = 0.f;

    for (int k0 = 0; k0 < K; k0 += BK) {
#pragma unroll
        for (int i = tid; i < BM * BK; i += 256) {
            int m = i / BK, k = i % BK;
            As[k][m] = A[(size_t)(bm + m) * K + k0 + k];
        }
#pragma unroll
        for (int i = tid; i < BN * BK; i += 256) {
            int n = i / BK, k = i % BK;
            float v = 0.f;
            if (bn + n < N) v = W[(size_t)(bn + n) * K + k0 + k];
            Ws[k][n] = v;
        }
        __syncthreads();
#pragma unroll
        for (int k = 0; k < BK; ++k) {
            float a[TM], w[TN];
#pragma unroll
            for (int i = 0; i < TM; i++) a[i] = As[k][ty * TM + i];
#pragma unroll
            for (int j = 0; j < TN; j++) w[j] = Ws[k][tx * TN + j];
#pragma unroll
            for (int i = 0; i < TM; i++)
#pragma unroll
                for (int j = 0; j < TN; j++) acc[i][j] = fmaf(a[i], w[j], acc[i][j]);
        }
        __syncthreads();
    }
#pragma unroll
    for (int i = 0; i < TM; i++) {
        int m = bm + ty * TM + i;
#pragma unroll
        for (int j = 0; j < TN; j++) {
            int n = bn + tx * TN + j;
            if (n < N) C[(size_t)m * N + n] = acc[i][j];
        }
    }
}

// ---------------- depthwise causal conv (k=4) + SiLU, 4 timesteps/thread ----------------
__global__ void conv_kernel(const float* __restrict__ conv_w, const float* __restrict__ conv_b) {
    int idx = blockIdx.x * blockDim.x + threadIdx.x;   // BL/4 * DI threads
    if (idx >= (BL / 4) * DI) return;
    int d   = idx % DI;
    int blk = idx / DI;
    int t0  = (blk % (LL / 4)) * 4;
    int b   = blk / (LL / 4);
    size_t bl0 = (size_t)b * LL + t0;
    const float* xcol = g_xz + bl0 * (2 * DI) + d;
    float w0 = conv_w[d * 4 + 0], w1 = conv_w[d * 4 + 1];
    float w2 = conv_w[d * 4 + 2], w3 = conv_w[d * 4 + 3];
    float bias = conv_b[d];
    float v[7];
#pragma unroll
    for (int k = -3; k <= 3; k++) {
        int t = t0 + k;
        v[k + 3] = (t >= 0) ? xcol[k * (2 * DI)] : 0.f;
    }
#pragma unroll
    for (int j = 0; j < 4; j++) {
        float acc = bias;
        acc = fmaf(w0, v[j],     acc);
        acc = fmaf(w1, v[j + 1], acc);
        acc = fmaf(w2, v[j + 2], acc);
        acc = fmaf(w3, v[j + 3], acc);
        float s = __fdividef(acc, 1.f + __expf(-acc));
        g_xconv[(bl0 + j) * DI + d] = s;
    }
}

// ---------------- dt projection + softplus + pack float4; also emits G = C*B ----------------
__global__ void dtpack_kernel(const float* __restrict__ W_dt, const float* __restrict__ b_dt,
                              const float* __restrict__ D_skip, const float* __restrict__ Cf) {
    int bl = blockIdx.x;          // 0..BL-1
    int d  = threadIdx.x;         // 0..383
    __shared__ float sx[DR];
    if (d < DR) sx[d] = g_xdb[(size_t)bl * NXDB + d];
    if (d < DS) g_G[(size_t)bl * DS + d] = g_xdb[(size_t)bl * NXDB + DR + d] * Cf[d];
    __syncthreads();
    float acc = b_dt[d];
#pragma unroll
    for (int r = 0; r < DR; r++) acc = fmaf(sx[r], W_dt[d * DR + r], acc);
    float dt = fmaxf(acc, 0.f) + __logf(1.f + __expf(-fabsf(acc)));
    float xc = g_xconv[(size_t)bl * DI + d];
    float z  = g_xz[(size_t)bl * (2 * DI) + DI + d];
    float sz = __fdividef(z, 1.f + __expf(-z));
    int b = bl / LL, l = bl % LL;
    g_P[((size_t)(b * DI + d)) * LL + l] = make_float4(dt, dt * xc, xc * D_skip[d], sz);
}

// ---------------- selective scan: warp per (b,d), G staged in smem ----------------
__global__ void __launch_bounds__(128) scan_kernel() {
    __shared__ float sG[32][64];          // 8 KB: G[t0..t0+31][0..63] for this block's b
    __shared__ float sred[4][32][33];
    const int wib  = threadIdx.x >> 5;
    const int warp = blockIdx.x * 4 + wib;
    const int lane = threadIdx.x & 31;
    const int b = warp / DI;
    const int d = warp % DI;

    const float4* __restrict__ p    = g_P + (size_t)warp * LL;
    const float*  __restrict__ Gsrc = g_G + (size_t)b * LL * DS;
    float* __restrict__ yp = g_y + (size_t)warp * LL;   // transposed [b][d][t]

    const float k1 = g_A[d * DS + 2 * lane]     * 1.44269504f;
    const float k2 = g_A[d * DS + 2 * lane + 1] * 1.44269504f;

    float h1 = 0.f, h2 = 0.f;
    float4 pk = p[0];
    float (*row)[33] = sred[wib];

    for (int t0 = 0; t0 < LL; t0 += 32) {
        __syncthreads();
        {
            const float4* gs4 = reinterpret_cast<const float4*>(Gsrc + (size_t)t0 * DS);
            float4* sg4 = reinterpret_cast<float4*>(&sG[0][0]);
            sg4[threadIdx.x]       = gs4[threadIdx.x];
            sg4[threadIdx.x + 128] = gs4[threadIdx.x + 128];
            sg4[threadIdx.x + 256] = gs4[threadIdx.x + 256];
            sg4[threadIdx.x + 384] = gs4[threadIdx.x + 384];
        }
        __syncthreads();

        float2 gv = *reinterpret_cast<const float2*>(&sG[0][2 * lane]);
#pragma unroll 8
        for (int j = 0; j < 32; ++j) {
            float4 pk_n = pk;
            float2 gv_n = gv;
            if (j < 31)
                gv_n = *reinterpret_cast<const float2*>(&sG[j + 1][2 * lane]);
            if (t0 + j + 1 < LL)
                pk_n = p[t0 + j + 1];
            float e1, e2;
            asm("ex2.approx.f32 %0, %1;" : "=f"(e1) : "f"(k1 * pk.x));
            asm("ex2.approx.f32 %0, %1;" : "=f"(e2) : "f"(k2 * pk.x));
            h1 = fmaf(e1, h1, pk.y * gv.x);
            h2 = fmaf(e2, h2, pk.y * gv.y);
            row[j][lane] = h1 + h2;
            pk = pk_n;
            gv = gv_n;
        }
        __syncwarp();
        float s0 = 0.f, s1 = 0.f, s2 = 0.f, s3 = 0.f;
#pragma unroll
        for (int i = 0; i < 32; i += 4) {
            s0 += row[lane][i + 0];
            s1 += row[lane][i + 1];
            s2 += row[lane][i + 2];
            s3 += row[lane][i + 3];
        }
        float4 q = p[t0 + lane];
        yp[t0 + lane] = ((s0 + s1) + (s2 + s3) + q.z) * q.w;
        __syncwarp();
    }
}

// ---------------- launch ----------------
extern "C" void kernel_launch(void* const* d_in, const int* in_sizes, int n_in,
                              void* d_out, int out_size) {
    const float* hidden  = (const float*)d_in[0];
    const float* resid   = (const float*)d_in[1];
    const float* ln_w    = (const float*)d_in[2];
    const float* ln_b    = (const float*)d_in[3];
    const float* W_in    = (const float*)d_in[4];
    const float* conv_w  = (const float*)d_in[5];
    const float* conv_b  = (const float*)d_in[6];
    const float* W_xproj = (const float*)d_in[7];
    const float* W_dt    = (const float*)d_in[8];
    const float* b_dt    = (const float*)d_in[9];
    const float* A_log   = (const float*)d_in[10];
    const float* D_skip  = (const float*)d_in[11];
    const float* C_fixed = (const float*)d_in[12];
    const float* W_out   = (const float*)d_in[13];

    float* out     = (float*)d_out;                    // (B,L,D)
    float* res_out = (float*)d_out + (size_t)BL * DD;  // (B,L,D)

    float* d_h;   cudaGetSymbolAddress((void**)&d_h,   g_h);
    float* d_xz;  cudaGetSymbolAddress((void**)&d_xz,  g_xz);
    float* d_xc;  cudaGetSymbolAddress((void**)&d_xc,  g_xconv);
    float* d_xdb; cudaGetSymbolAddress((void**)&d_xdb, g_xdb);
    float* d_y;   cudaGetSymbolAddress((void**)&d_y,   g_y);

    // 0) A = -exp(A_log)
    prep_A_kernel<<<(DI * DS + 255) / 256, 256>>>(A_log);

    // 1) residual add + LN
    ln_kernel<<<BL / 8, 256>>>(hidden, resid, ln_w, ln_b, res_out);

    // 2) xz = h @ W_in^T   (M=8192, N=768, K=192) — TF32, cp.async pipelined
    {
        dim3 grid(768 / 64, BL / 128);
        gemm_tf32<false><<<grid, 256>>>(d_h, W_in, d_xz, BL, 2 * DI, DD);
    }

    // 3) depthwise causal conv + silu (4 t/thread)
    conv_kernel<<<((BL / 4) * DI + 255) / 256, 256>>>(conv_w, conv_b);

    // 4) xdb = xconv @ W_xproj^T  (M=8192, N=76, K=384) — fp32 (feeds exp path)
    {
        dim3 grid((NXDB + 63) / 64, BL / 128);
        gemm_nt<128, 64, 16, 8, 4><<<grid, 256>>>(d_xc, W_xproj, d_xdb, BL, NXDB, DI);
    }

    // 5+6) G = C*B fused into dt / pack
    dtpack_kernel<<<BL, DI>>>(W_dt, b_dt, D_skip, C_fixed);

    // 7) scan
    scan_kernel<<<(BB * DI) / 4, 128>>>();

    // 8) out = y^T @ W_out^T  (M=8192, N=192, K=384) — TF32, cp.async pipelined
    {
        dim3 grid(DD / 64, BL / 128);
        gemm_tf32<true><<<grid, 256>>>(d_y, W_out, out, BL, DD, DI);
    }
}